// round 17
// baseline (speedup 1.0000x reference)
#include <cuda_runtime.h>
#include <stdint.h>

#define BB 8
#define NN 4096
#define KC 37
#define CHP 111
#define TILE 32
#define TTILES 4
#define PART (3*64*64)

__device__ float g_part[BB*KC*PART];
__device__ float g_dens[BB*4096];

typedef unsigned long long u64;

__device__ __forceinline__ float ex2f(float x){float r;asm("ex2.approx.f32 %0,%1;":"=f"(r):"f"(x));return r;}
#define FMA2(d,a,b) asm("fma.rn.f32x2 %0,%1,%2,%0;":"+l"(d):"l"(a),"l"(b))
#define MUL2(d,a,b) asm("mul.rn.f32x2 %0,%1,%2;":"=l"(d):"l"(a),"l"(b))
#define PACK2(d,f)  asm("mov.b64 %0,{%1,%1};":"=l"(d):"f"(f))

// dynamic smem layout (floats): RF 2x32x66 | CFdup 2x32x132 | sP 3x32x8
#define SRF(bb,p,i) smf[((bb)*TILE+(p))*66 + (i)]
#define SCF(bb,p,i) smf[4224 + ((bb)*TILE+(p))*132 + (i)]
#define SPT(s,p,i)  smf[12672 + ((s)*TILE+(p))*8 + (i)]
#define SMEM_BYTES (13440*4)

__global__ void __launch_bounds__(384,2)
rbf_partial_kernel(const float* __restrict__ xc, const float* __restrict__ yc,
                   const float* __restrict__ tc, const int* __restrict__ mask){
  extern __shared__ float smf[];
  const int tid=threadIdx.x;
  const int b=blockIdx.y, kc=blockIdx.x;
  const float CEXP=-72.13475204444817f, STEP=2.0f/63.0f;
  const float TK1=CEXP*STEP*STEP, TK2=-2.0f*CEXP*STEP;
  const float C2=ex2f(2.0f*TK1);
  const int p0=kc*CHP, p1=min(p0+CHP,NN);

  if(tid>=256){
    // ───── producers: 4 warps. warp u: u<2 -> RF rows [32u,32u+32);
    //       u>=2 -> CF cols [32(u-2),...). lane = point. 32-step recurrence.
    const int ptid=tid-256, u=ptid>>5, lane=ptid&31;

#define LOADSTSP(tt) do{ if(lane<8 && (tt)<TTILES){                           \
      const int pl=u*8+lane; const int sp_=(tt)%3;                            \
      const int n=p0+(tt)*TILE+pl;                                            \
      float px=0.f,py=0.f,mf=0.f,yv=0.f,tv=0.f;                               \
      if(n<p1){ px=xc[(b*NN+n)*2]; py=xc[(b*NN+n)*2+1];                       \
        mf=(mask[b*NN+n]!=0)?0.0f:1.0f; yv=yc[b*NN+n]; tv=tc[b*NN+n]; }       \
      SPT(sp_,pl,0)=px; SPT(sp_,pl,1)=py; SPT(sp_,pl,2)=mf;                   \
      SPT(sp_,pl,4)=yv; SPT(sp_,pl,5)=yv; SPT(sp_,pl,6)=tv; SPT(sp_,pl,7)=tv; \
    } }while(0)

#define STAGE_A(tt) do{                                                       \
      const int bb_=(tt)&1, sp_=(tt)%3;                                       \
      if(u<2){                                                                \
        const float g0=-1.f+STEP*(float)(u*32);                               \
        const float d0=SPT(sp_,lane,1)-g0;                                    \
        float wv=ex2f(CEXP*d0*d0), tv=ex2f(TK1+TK2*d0);                       \
        _Pragma("unroll")                                                     \
        for(int j=0;j<32;j++){ SRF(bb_,lane,u*32+j)=wv; wv*=tv; tv*=C2; }     \
      }else{                                                                  \
        const int s=u-2;                                                      \
        const float g0=-1.f+STEP*(float)(s*32);                               \
        const float d0=SPT(sp_,lane,0)-g0;                                    \
        float wv=ex2f(CEXP*d0*d0)*SPT(sp_,lane,2), tv=ex2f(TK1+TK2*d0);       \
        _Pragma("unroll")                                                     \
        for(int j=0;j<32;j++){ u64 dd; PACK2(dd,wv);                          \
          *(u64*)&SCF(bb_,lane,2*(s*32+j))=dd; wv*=tv; tv*=C2; }              \
      } }while(0)

    LOADSTSP(0);
    __syncthreads();
    LOADSTSP(1);
    STAGE_A(0);
    __syncthreads();
#pragma unroll 1
    for(int t=0;t<TTILES;t++){
      LOADSTSP(t+2);
      if(t+1<TTILES) STAGE_A(t+1);
      __syncthreads();
    }
  } else {
    // ───── consumers: 8 warps. warp w = col-octave, lane = row-pair.
    const int w=tid>>5, lane=tid&31, row0=lane<<1, w16=w*16;
    u64 acc[3][8];
#pragma unroll
    for(int ch=0;ch<3;ch++)
#pragma unroll
      for(int c=0;c<8;c++) acc[ch][c]=0ULL;

    __syncthreads();   // match producer prologue
    __syncthreads();
#pragma unroll 1
    for(int t=0;t<TTILES;t++){
      const int bb=t&1, sp=t%3;
#pragma unroll 4
      for(int p=0;p<TILE;p++){
        const u64 r0=*(const u64*)&SRF(bb,p,row0);      // wy row-pair
        const u64 yp=*(const u64*)&SPT(sp,p,4);         // {y,y} broadcast
        const u64 tp=*(const u64*)&SPT(sp,p,6);         // {t,t} broadcast
        u64 r1,r2; MUL2(r1,r0,yp); MUL2(r2,r0,tp);
        {
          const float4 f0=*(const float4*)&SCF(bb,p,w16);
          const float4 f1=*(const float4*)&SCF(bb,p,w16+4);
          const u64* c0=(const u64*)&f0; const u64* c1=(const u64*)&f1;
          FMA2(acc[0][0],r0,c0[0]); FMA2(acc[0][1],r0,c0[1]);
          FMA2(acc[0][2],r0,c1[0]); FMA2(acc[0][3],r0,c1[1]);
          FMA2(acc[1][0],r1,c0[0]); FMA2(acc[1][1],r1,c0[1]);
          FMA2(acc[1][2],r1,c1[0]); FMA2(acc[1][3],r1,c1[1]);
          FMA2(acc[2][0],r2,c0[0]); FMA2(acc[2][1],r2,c0[1]);
          FMA2(acc[2][2],r2,c1[0]); FMA2(acc[2][3],r2,c1[1]);
        }
        {
          const float4 f2=*(const float4*)&SCF(bb,p,w16+8);
          const float4 f3=*(const float4*)&SCF(bb,p,w16+12);
          const u64* c2=(const u64*)&f2; const u64* c3=(const u64*)&f3;
          FMA2(acc[0][4],r0,c2[0]); FMA2(acc[0][5],r0,c2[1]);
          FMA2(acc[0][6],r0,c3[0]); FMA2(acc[0][7],r0,c3[1]);
          FMA2(acc[1][4],r1,c2[0]); FMA2(acc[1][5],r1,c2[1]);
          FMA2(acc[1][6],r1,c3[0]); FMA2(acc[1][7],r1,c3[1]);
          FMA2(acc[2][4],r2,c2[0]); FMA2(acc[2][5],r2,c2[1]);
          FMA2(acc[2][6],r2,c3[0]); FMA2(acc[2][7],r2,c3[1]);
        }
      }
      __syncthreads();
    }

    // epilogue -> transposed partials [ch][col][row]; u64 stores, lanes
    // cover rows 0..63 per (ch,c): coalesced 256B
    float* dst=&g_part[(b*KC+kc)*PART];
#pragma unroll
    for(int ch=0;ch<3;ch++)
#pragma unroll
      for(int c=0;c<8;c++)
        *(u64*)&dst[ch*4096 + (8*w+c)*64 + row0]=acc[ch][c];
  }
}

// K2: density; coalesced transposed reads; out (de-transposed) + scratch
__global__ __launch_bounds__(256)
void rbf_density_kernel(float* __restrict__ out){
  const int idx=blockIdx.x*blockDim.x+threadIdx.x;   // 32768
  const int b=idx>>12, gp=idx&4095;
  const int row=gp&63, col=gp>>6;
  const float* base=&g_part[b*KC*PART]+gp;
  float s=0.f;
#pragma unroll
  for(int k=0;k<KC;k++) s+=base[k*PART];
  g_dens[b*4096+gp]=s;
  out[b*12288+row*64+col]=s;
}

// K3: weighted channels / (density + eps); all reads coalesced
__global__ __launch_bounds__(256)
void rbf_weighted_kernel(float* __restrict__ out){
  const int idx=blockIdx.x*blockDim.x+threadIdx.x;   // 65536
  const int b=idx>>13, r=idx&8191;
  const int ch=1+(r>>12), gp=r&4095;
  const int row=gp&63, col=gp>>6;
  const float* base=&g_part[b*KC*PART+ch*4096]+gp;
  float s=0.f;
#pragma unroll
  for(int k=0;k<KC;k++) s+=base[k*PART];
  out[b*12288+ch*4096+row*64+col]=s/(g_dens[b*4096+gp]+1e-5f);
}

extern "C" void kernel_launch(void* const* d_in,const int* in_sizes,int n_in,
                              void* d_out,int out_size){
  const float* xc=(const float*)d_in[0];
  const float* yc=(const float*)d_in[1];
  const float* tc=(const float*)d_in[2];
  const int*  mk=(const int*)d_in[3];

  cudaFuncSetAttribute(rbf_partial_kernel,
                       cudaFuncAttributeMaxDynamicSharedMemorySize, SMEM_BYTES);
  dim3 grid(KC,BB);
  rbf_partial_kernel<<<grid,384,SMEM_BYTES>>>(xc,yc,tc,mk);
  rbf_density_kernel<<<128,256>>>((float*)d_out);
  rbf_weighted_kernel<<<256,256>>>((float*)d_out);
}